// round 1
// baseline (speedup 1.0000x reference)
#include <cuda_runtime.h>
#include <math.h>

#define SEQ    2048
#define DM     768
#define NH     4
#define HD     192
#define BATCH  4
#define BHT    16           // BATCH*NH
#define NEGV   (-1000000000.0f)

// ---- device scratch (allocation-free rule: static __device__ arrays) ----
__device__ float g_Q [BHT*SEQ*HD];
__device__ float g_K [BHT*SEQ*HD];
__device__ float g_V [BHT*SEQ*HD];
__device__ float g_X1[BHT*SEQ*HD];
__device__ float g_Sc[BHT*SEQ*SEQ];      // 268 MB raw masked scores
__device__ float g_cm[BHT*SEQ];          // per-column max
__device__ float g_ci[BHT*SEQ];          // per-column 1/sum

// ============================================================
// K1: QKV projection.  C = X @ W^T + b   (NT GEMM, 64x64x16 tiles)
// X: [8192, 768] row-major; W: [768, 768] row-major (output-major, K-contig)
// Out layout: (b, h, s, d)
// ============================================================
__global__ __launch_bounds__(256) void k_qkv(
    const float* __restrict__ X,
    const float* __restrict__ Wq, const float* __restrict__ bq,
    const float* __restrict__ Wk, const float* __restrict__ bk,
    const float* __restrict__ Wv, const float* __restrict__ bv)
{
    int w = blockIdx.z;
    const float* W    = (w==0)?Wq:((w==1)?Wk:Wv);
    const float* bias = (w==0)?bq:((w==1)?bk:bv);
    float* Out        = (w==0)?g_Q:((w==1)?g_K:g_V);

    int m0 = blockIdx.y * 64;
    int n0 = blockIdx.x * 64;
    int tid = threadIdx.x;
    int tx = tid & 15, ty = tid >> 4;

    __shared__ float As[64][17];
    __shared__ float Bs[64][17];
    float acc[4][4] = {};

    for (int kb = 0; kb < DM; kb += 16) {
        #pragma unroll
        for (int r = 0; r < 4; r++) {
            int e = tid + 256*r;
            int row = e >> 4, col = e & 15;
            As[row][col] = X[(m0+row)*DM + kb + col];
            Bs[row][col] = W[(n0+row)*DM + kb + col];
        }
        __syncthreads();
        #pragma unroll
        for (int kk = 0; kk < 16; kk++) {
            float a[4], b[4];
            #pragma unroll
            for (int i=0;i<4;i++) a[i] = As[ty*4+i][kk];
            #pragma unroll
            for (int j=0;j<4;j++) b[j] = Bs[tx*4+j][kk];
            #pragma unroll
            for (int i=0;i<4;i++)
                #pragma unroll
                for (int j=0;j<4;j++) acc[i][j] += a[i]*b[j];
        }
        __syncthreads();
    }

    #pragma unroll
    for (int i=0;i<4;i++){
        int ig = m0 + ty*4 + i;                 // global row in [0, B*S)
        int b_ = ig >> 11, s_ = ig & (SEQ-1);
        #pragma unroll
        for (int j=0;j<4;j++){
            int jg = n0 + tx*4 + j;             // global col in [0, 768)
            int h_ = jg / HD, d_ = jg % HD;
            Out[((b_*NH + h_)*SEQ + s_)*HD + d_] = acc[i][j] + bias[jg];
        }
    }
}

// ============================================================
// K2: scores = Q @ K^T / 20, causal + pad mask, lower-tri tiles only
// ============================================================
__global__ __launch_bounds__(256) void k_scores(const unsigned char* __restrict__ am)
{
    int bh = blockIdx.y;
    int b_ = bh >> 2;
    int t  = blockIdx.x;
    // map linear tri index -> (qt, kt), kt <= qt
    int qt = (int)floorf((sqrtf(8.0f*(float)t + 1.0f) - 1.0f) * 0.5f);
    while ((qt+1)*(qt+2)/2 <= t) ++qt;
    while (qt*(qt+1)/2 > t)      --qt;
    int kt = t - qt*(qt+1)/2;

    int q0 = qt*64, k0 = kt*64;
    const float* Qp = g_Q + (size_t)bh*SEQ*HD;
    const float* Kp = g_K + (size_t)bh*SEQ*HD;

    int tid = threadIdx.x;
    int tx = tid & 15, ty = tid >> 4;

    __shared__ float As[64][17];
    __shared__ float Bs[64][17];
    float acc[4][4] = {};

    for (int kb = 0; kb < HD; kb += 16) {
        #pragma unroll
        for (int r = 0; r < 4; r++) {
            int e = tid + 256*r;
            int row = e >> 4, col = e & 15;
            As[row][col] = Qp[(q0+row)*HD + kb + col];
            Bs[row][col] = Kp[(k0+row)*HD + kb + col];
        }
        __syncthreads();
        #pragma unroll
        for (int kk = 0; kk < 16; kk++) {
            float a[4], b[4];
            #pragma unroll
            for (int i=0;i<4;i++) a[i] = As[ty*4+i][kk];
            #pragma unroll
            for (int j=0;j<4;j++) b[j] = Bs[tx*4+j][kk];
            #pragma unroll
            for (int i=0;i<4;i++)
                #pragma unroll
                for (int j=0;j<4;j++) acc[i][j] += a[i]*b[j];
        }
        __syncthreads();
    }

    #pragma unroll
    for (int i=0;i<4;i++){
        int q = q0 + ty*4 + i;
        bool pad = am[b_*SEQ + q] != 0;
        #pragma unroll
        for (int j=0;j<4;j++){
            int k = k0 + tx*4 + j;
            float v = (k > q || pad) ? NEGV : acc[i][j]*0.05f;
            g_Sc[((long long)(bh*SEQ + q))*SEQ + k] = v;
        }
    }
}

// ============================================================
// K3: per-key-column online (max, sum of exp).  One block per (kt, bh).
// ============================================================
__global__ __launch_bounds__(256) void k_stats()
{
    int kt = blockIdx.x, bh = blockIdx.y;
    int tid = threadIdx.x;
    int kx = tid & 63, qg = tid >> 6;       // 64 columns x 4 q-strides
    int k = kt*64 + kx;

    float m = -3.4e38f, l = 0.0f;
    for (int q = kt*64 + qg; q < SEQ; q += 4) {
        float s = g_Sc[((long long)(bh*SEQ + q))*SEQ + k];
        if (s > m) { l = l*__expf(m - s) + 1.0f; m = s; }
        else       { l += __expf(s - m); }
    }

    __shared__ float sm[4][64], sl[4][64];
    sm[qg][kx] = m; sl[qg][kx] = l;
    __syncthreads();
    if (qg == 0) {
        float M = m, L = l;
        #pragma unroll
        for (int g = 1; g < 4; g++) {
            float mg = sm[g][kx], lg = sl[g][kx];
            float Mn = fmaxf(M, mg);
            L = L*__expf(M - Mn) + lg*__expf(mg - Mn);
            M = Mn;
        }
        g_cm[bh*SEQ + k] = M;
        g_ci[bh*SEQ + k] = 1.0f / L;
    }
}

// ============================================================
// K4: X1 = P @ V, P computed on the fly from raw scores.
// Block: 64 q-rows x full 192 d-cols (exp + score read happen once).
// ============================================================
__global__ __launch_bounds__(256) void k_av()
{
    int qt = (SEQ/64 - 1) - blockIdx.x;     // longest blocks first
    int bh = blockIdx.y;
    int q0 = qt*64;
    int kmax = (qt+1)*64;

    const float* Vp = g_V + (size_t)bh*SEQ*HD;
    const float* cm = g_cm + bh*SEQ;
    const float* ci = g_ci + bh*SEQ;

    int tid = threadIdx.x;
    int tx = tid & 15, ty = tid >> 4;       // cols tx*12..+11, rows ty*4..+3

    __shared__ float Ps[64][17];
    __shared__ float Vs[16][193];
    float acc[4][12] = {};

    for (int k0 = 0; k0 < kmax; k0 += 16) {
        // load P tile (64 q x 16 k), applying exp/normalize inline
        #pragma unroll
        for (int r = 0; r < 4; r++) {
            int e = tid + 256*r;
            int row = e >> 4, col = e & 15;
            int k = k0 + col;
            float s = g_Sc[((long long)(bh*SEQ + q0 + row))*SEQ + k];
            Ps[row][col] = __expf(s - __ldg(&cm[k])) * __ldg(&ci[k]);
        }
        // load V tile (16 k x 192 d)
        #pragma unroll
        for (int r = 0; r < 12; r++) {
            int e = tid + 256*r;
            int vr = e / 192, vc = e - vr*192;
            Vs[vr][vc] = Vp[(k0+vr)*HD + vc];
        }
        __syncthreads();
        #pragma unroll
        for (int kk = 0; kk < 16; kk++) {
            float a[4];
            #pragma unroll
            for (int i=0;i<4;i++) a[i] = Ps[ty*4+i][kk];
            #pragma unroll
            for (int j=0;j<12;j++) {
                float bv = Vs[kk][tx*12+j];
                #pragma unroll
                for (int i=0;i<4;i++) acc[i][j] += a[i]*bv;
            }
        }
        __syncthreads();
    }

    #pragma unroll
    for (int i=0;i<4;i++){
        int q = q0 + ty*4 + i;
        #pragma unroll
        for (int j=0;j<12;j++){
            g_X1[(bh*SEQ + q)*HD + tx*12 + j] = acc[i][j];
        }
    }
}

// ============================================================
// K5: y = x + X1 (re-gathered), LayerNorm(y) * gamma + beta
// ============================================================
__global__ __launch_bounds__(256) void k_ln(
    const float* __restrict__ x,
    const float* __restrict__ gamma,
    const float* __restrict__ beta,
    float* __restrict__ out)
{
    int row = blockIdx.x;
    int b_ = row >> 11, s_ = row & (SEQ-1);
    int tid = threadIdx.x;

    __shared__ float ybuf[DM];
    __shared__ float rs[32], rq[32];
    __shared__ float s_mu, s_inv;

    float sum = 0.0f, sq = 0.0f;
    for (int c = tid; c < DM; c += 256) {
        int h_ = c / HD, d_ = c - h_*HD;
        float v = x[row*DM + c] + g_X1[((b_*NH + h_)*SEQ + s_)*HD + d_];
        ybuf[c] = v;
        sum += v; sq += v*v;
    }
    #pragma unroll
    for (int o = 16; o; o >>= 1) {
        sum += __shfl_down_sync(0xffffffffu, sum, o);
        sq  += __shfl_down_sync(0xffffffffu, sq , o);
    }
    int wid = tid >> 5, lane = tid & 31;
    if (lane == 0) { rs[wid] = sum; rq[wid] = sq; }
    __syncthreads();
    if (tid < 32) {
        sum = (tid < 8) ? rs[tid] : 0.0f;
        sq  = (tid < 8) ? rq[tid] : 0.0f;
        #pragma unroll
        for (int o = 4; o; o >>= 1) {
            sum += __shfl_down_sync(0xffffffffu, sum, o);
            sq  += __shfl_down_sync(0xffffffffu, sq , o);
        }
        if (tid == 0) {
            float mu  = sum * (1.0f/DM);
            float var = sq  * (1.0f/DM) - mu*mu;
            s_mu = mu;
            s_inv = rsqrtf(var + 1e-5f);
        }
    }
    __syncthreads();
    float mu = s_mu, inv = s_inv;
    for (int c = tid; c < DM; c += 256)
        out[row*DM + c] = (ybuf[c] - mu)*inv*gamma[c] + beta[c];
}

// ============================================================
extern "C" void kernel_launch(void* const* d_in, const int* in_sizes, int n_in,
                              void* d_out, int out_size)
{
    const float*         x     = (const float*)d_in[0];
    const unsigned char* am    = (const unsigned char*)d_in[1];
    const float*         Wq    = (const float*)d_in[2];
    const float*         bq    = (const float*)d_in[3];
    const float*         Wk    = (const float*)d_in[4];
    const float*         bk    = (const float*)d_in[5];
    const float*         Wv    = (const float*)d_in[6];
    const float*         bv    = (const float*)d_in[7];
    const float*         gamma = (const float*)d_in[8];
    const float*         beta  = (const float*)d_in[9];
    float*               out   = (float*)d_out;

    (void)in_sizes; (void)n_in; (void)out_size;

    dim3 g1(DM/64, (BATCH*SEQ)/64, 3);
    k_qkv<<<g1, 256>>>(x, Wq, bq, Wk, bk, Wv, bv);

    const int NT = (SEQ/64)*(SEQ/64 + 1)/2;   // 528 lower-tri tiles
    k_scores<<<dim3(NT, BHT), 256>>>(am);

    k_stats<<<dim3(SEQ/64, BHT), 256>>>();

    k_av<<<dim3(SEQ/64, BHT), 256>>>();

    k_ln<<<BATCH*SEQ, 256>>>(x, gamma, beta, out);
}